// round 15
// baseline (speedup 1.0000x reference)
#include <cuda_runtime.h>
#include <cuda_bf16.h>
#include <cuda_fp16.h>

// Fixed shapes from setup_inputs: structure int32[32,32,32,32], PS=4
#define BB 32
#define DD 32
#define HH 32
#define WW 32
#define SLABS_PER_BLOCK 2
#define GRID_BLOCKS 1024               // 2048 slabs / 2
#define PATCHES_PER_BLOCK 16
#define TOTAL_PATCHES 16384
#define TOTAL_WARPS (GRID_BLOCKS * 4)  // one packed atomic per WARP
#define AIR0 102
#define AIR1 576
#define AIR2 3352
#define SENT_BASE 0x5000               // sentinels: 0x5000+slot, normal fp16,
                                       // disjoint from biased tokens (0x4000..0x4E85)
#define FP_SCALE 4294967296.0          // 2^32 fixed-point scale
// Packed-accumulator: bits [0,52) fixed-point sum (+ per-warp bias),
// bits [52,64) warp-arrival count. One atomicAdd does sum + count at once.
// 4096 warps x 2^38 bias = 2^50; max entropy sum ~2^48.1; total < 2^52. OK.
#define WARP_BIAS (1ULL << 38)
#define CNT_ONE   (1ULL << 52)
#define SUM_MASK  (CNT_ONE - 1ULL)

// Zero-initialized at module load; last warp resets it (graph-replay safe).
__device__ unsigned long long g_acc = 0ULL;

// Two compares + two accumulates in 2 instructions, one per pipe:
//   set.eq.f16x2 (alu: HSET2) + add.rn.f16x2 (fma: HADD2).
#define SETEQ_ACC(acc, u, vv) \
    asm("{.reg .b32 t; set.eq.f16x2.f16x2 t, %1, %2; add.rn.f16x2 %0, %0, t;}" \
        : "+r"(acc) : "r"(u), "r"(vv))

// one packed tile u32 vs all 8 probes: 16 compares, 16 inst, 8 indep chains
#define CMP8(u1) do { \
    SETEQ_ACC(acc0, u1, vv0); SETEQ_ACC(acc1, u1, vv1); \
    SETEQ_ACC(acc2, u1, vv2); SETEQ_ACC(acc3, u1, vv3); \
    SETEQ_ACC(acc4, u1, vv4); SETEQ_ACC(acc5, u1, vv5); \
    SETEQ_ACC(acc6, u1, vv6); SETEQ_ACC(acc7, u1, vv7); \
} while (0)

__device__ __forceinline__ unsigned prmt(unsigned a, unsigned b, unsigned sel) {
    unsigned d;
    asm("prmt.b32 %0, %1, %2, %3;" : "=r"(d) : "r"(a), "r"(b), "r"(sel));
    return d;
}

// half2 -> exact small-int count (counts <= 64 are exact in fp16)
__device__ __forceinline__ int h2_count(unsigned acc) {
    const __half2 h = *(const __half2*)&acc;
    const __half s = __hadd(__low2half(h), __high2half(h));
    int r;
    asm("cvt.rni.s32.f16 %0, %1;" : "=r"(r) : "h"(*(const unsigned short*)&s));
    return r;
}

// air token -> per-slot-unique sentinel (count 1 => log 0 => invisible);
// else biased token (normal fp16 bit pattern).
__device__ __forceinline__ unsigned stage16(int v, int slot) {
    const bool air = (v == AIR0) | (v == AIR1) | (v == AIR2);
    return air ? (unsigned)(SENT_BASE + slot) : ((unsigned)v | 0x4000u);
}

// 128 threads, 16 patches/block (two slabs), 8 tokens per thread (8 thr/patch).
// Epilogue: ONE warp-level reduce + one packed atomic per warp. No second
// barrier, no cross-warp smem reduction.
__global__ __launch_bounds__(128)
void patch_entropy_fused_kernel(const int* __restrict__ s, float* __restrict__ out) {
    // patch stride 36 u32 (32 data + 4 pad = 144B): 16B-aligned, bank-spread
    __shared__ unsigned sm32[PATCHES_PER_BLOCK * 36];
    __shared__ float logtab[65];   // log(i), log(0):=0
    __shared__ float invtab[65];   // 1/i,    1/0 :=0

    const int tid = threadIdx.x;

    // ---- LUT init (one-time MUFUs, off the hot path) ----
    if (tid < 65) {
        const float fi = (float)tid;
        logtab[tid] = (tid == 0) ? 0.0f : __logf(fi);
        invtab[tid] = (tid == 0) ? 0.0f : __fdividef(1.0f, fi);
    }

    // ---- geometry: thread owns 8 contiguous token slots of patch pp ----
    const int pp = tid >> 3;            // 0..15
    const int r  = tid & 7;             // eighth of patch; slots 8r..8r+7
    const int d  = r >> 1;              // 0..3
    const int h0 = (r & 1) << 1;        // 0 or 2 (two h-rows)
    const int w4 = pp & 7;
    const int gslab = blockIdx.x * SLABS_PER_BLOCK + (pp >> 3);
    const int b  = gslab >> 6;
    const int pd = (gslab >> 3) & 7;
    const int ph = gslab & 7;
    const int base = b * (DD * HH * WW) + pd * (4 * HH * WW) + ph * (4 * WW)
                   + d * (HH * WW) + h0 * WW + w4 * 4;

    // ---- two LDG.128 (own 8 tokens), sentinel substitution, pack u16x2 ----
    const int4 va = *(const int4*)(s + base);
    const int4 vb = *(const int4*)(s + base + WW);
    const int slot = r << 3;
    const unsigned p0 = stage16(va.x, slot)     | (stage16(va.y, slot + 1) << 16);
    const unsigned p1 = stage16(va.z, slot + 2) | (stage16(va.w, slot + 3) << 16);
    const unsigned p2 = stage16(vb.x, slot + 4) | (stage16(vb.y, slot + 5) << 16);
    const unsigned p3 = stage16(vb.z, slot + 6) | (stage16(vb.w, slot + 7) << 16);
    *(uint4*)&sm32[pp * 36 + (r << 2)] = make_uint4(p0, p1, p2, p3);

    // probes (register-resident, no smem reload)
    const unsigned vv0 = prmt(p0, p0, 0x1010);
    const unsigned vv1 = prmt(p0, p0, 0x3232);
    const unsigned vv2 = prmt(p1, p1, 0x1010);
    const unsigned vv3 = prmt(p1, p1, 0x3232);
    const unsigned vv4 = prmt(p2, p2, 0x1010);
    const unsigned vv5 = prmt(p2, p2, 0x3232);
    const unsigned vv6 = prmt(p3, p3, 0x1010);
    const unsigned vv7 = prmt(p3, p3, 0x3232);

    // non-air among own 8 tokens (sentinel <=> staged >= SENT_BASE)
    int na = 8;
    na -= ((p0 & 0xFFFFu) >= SENT_BASE) + ((p0 >> 16) >= SENT_BASE);
    na -= ((p1 & 0xFFFFu) >= SENT_BASE) + ((p1 >> 16) >= SENT_BASE);
    na -= ((p2 & 0xFFFFu) >= SENT_BASE) + ((p2 >> 16) >= SENT_BASE);
    na -= ((p3 & 0xFFFFu) >= SENT_BASE) + ((p3 >> 16) >= SENT_BASE);

    // tot over the 8-lane patch segment (xor offsets stay in segment)
    int tot = na;
    tot += __shfl_xor_sync(0xFFFFFFFFu, tot, 1);
    tot += __shfl_xor_sync(0xFFFFFFFFu, tot, 2);
    tot += __shfl_xor_sync(0xFFFFFFFFu, tot, 4);

    __syncthreads();

    // ---- compare core: 8x LDS.128 (pipelined) x 8 probes, f16x2 SIMD ----
    const uint4* pbase4 = (const uint4*)&sm32[pp * 36];
    unsigned acc0 = 0, acc1 = 0, acc2 = 0, acc3 = 0;
    unsigned acc4 = 0, acc5 = 0, acc6 = 0, acc7 = 0;
    uint4 u = pbase4[0];
    #pragma unroll
    for (int k = 0; k < 8; ++k) {
        const uint4 nxt = pbase4[(k + 1) & 7];   // k==7 wraps: harmless reload
        CMP8(u.x);
        CMP8(u.y);
        CMP8(u.z);
        CMP8(u.w);
        u = nxt;
    }

    // Branch-free epilogue: sentinels have c==1 -> logtab[1]==0 -> contribute 0.
    const float sl = logtab[h2_count(acc0)] + logtab[h2_count(acc1)]
                   + logtab[h2_count(acc2)] + logtab[h2_count(acc3)]
                   + logtab[h2_count(acc4)] + logtab[h2_count(acc5)]
                   + logtab[h2_count(acc6)] + logtab[h2_count(acc7)];
    const float term = invtab[tot] * fmaf((float)na, logtab[tot], -sl);

    // ---- warp-level sum (4 whole patches per warp) -> ONE atomic per warp ----
    float x = term;
    #pragma unroll
    for (int off = 16; off > 0; off >>= 1)
        x += __shfl_xor_sync(0xFFFFFFFFu, x, off);

    if ((tid & 31) == 0) {
        // Packed atomic: fixed-point sum + warp-arrival count in one u64.
        // Integer adds are order-invariant => bit-deterministic. The LAST
        // warp's atomic return already contains every other warp's
        // contribution — no fence, no ticket, no barrier, no re-read.
        const long long sfp = (long long)((double)x * FP_SCALE);
        const unsigned long long qv =
            (unsigned long long)(sfp + (long long)WARP_BIAS) | CNT_ONE;
        const unsigned long long old = atomicAdd(&g_acc, qv);
        if ((old >> 52) == (TOTAL_WARPS - 1)) {
            const unsigned long long sum52 = (old + qv) & SUM_MASK;
            const double total =
                ((double)(long long)(sum52 - (unsigned long long)TOTAL_WARPS * WARP_BIAS))
                / FP_SCALE;
            out[0] = (float)(total / ((double)TOTAL_PATCHES + 1e-06));
            g_acc = 0ULL;   // self-clean for the next graph replay
        }
    }
}

extern "C" void kernel_launch(void* const* d_in, const int* in_sizes, int n_in,
                              void* d_out, int out_size) {
    const int* structure = (const int*)d_in[0];
    float* out = (float*)d_out;
    patch_entropy_fused_kernel<<<GRID_BLOCKS, 128>>>(structure, out);
}

// round 16
// speedup vs baseline: 1.0617x; 1.0617x over previous
#include <cuda_runtime.h>
#include <cuda_bf16.h>
#include <cuda_fp16.h>

// Fixed shapes from setup_inputs: structure int32[32,32,32,32], PS=4
#define BB 32
#define DD 32
#define HH 32
#define WW 32
#define SLABS_PER_BLOCK 2
#define GRID_BLOCKS 1024               // 2048 slabs / 2
#define PATCHES_PER_BLOCK 16
#define TOTAL_PATCHES 16384
#define AIR0 102
#define AIR1 576
#define AIR2 3352
#define SENT_BASE 0x5000               // sentinels: 0x5000+slot, normal fp16,
                                       // disjoint from biased tokens (0x4000..0x4E85)
#define FP_SCALE 4294967296.0          // 2^32 fixed-point scale
// Packed-accumulator: bits [0,52) fixed-point sum (+ per-block bias),
// bits [52,64) block-arrival count. One atomicAdd does sum + count at once.
#define BLK_BIAS (1ULL << 40)
#define CNT_ONE  (1ULL << 52)
#define SUM_MASK (CNT_ONE - 1ULL)

// Zero-initialized at module load; last block resets it (graph-replay safe).
__device__ unsigned long long g_acc = 0ULL;

// Two compares + two accumulates in 2 instructions, one per pipe:
//   set.eq.f16x2 (alu: HSET2) + add.rn.f16x2 (fma: HADD2).
#define SETEQ_ACC(acc, u, vv) \
    asm("{.reg .b32 t; set.eq.f16x2.f16x2 t, %1, %2; add.rn.f16x2 %0, %0, t;}" \
        : "+r"(acc) : "r"(u), "r"(vv))

// one packed tile u32 vs all 8 probes: 16 compares, 16 inst, 8 indep chains
#define CMP8(u1) do { \
    SETEQ_ACC(acc0, u1, vv0); SETEQ_ACC(acc1, u1, vv1); \
    SETEQ_ACC(acc2, u1, vv2); SETEQ_ACC(acc3, u1, vv3); \
    SETEQ_ACC(acc4, u1, vv4); SETEQ_ACC(acc5, u1, vv5); \
    SETEQ_ACC(acc6, u1, vv6); SETEQ_ACC(acc7, u1, vv7); \
} while (0)

__device__ __forceinline__ unsigned prmt(unsigned a, unsigned b, unsigned sel) {
    unsigned d;
    asm("prmt.b32 %0, %1, %2, %3;" : "=r"(d) : "r"(a), "r"(b), "r"(sel));
    return d;
}

// half2 accumulator -> exact count as float (counts <= 64 exact in fp16)
__device__ __forceinline__ float h2_countf(unsigned acc) {
    const __half2 h = *(const __half2*)&acc;
    return __low2float(h) + __high2float(h);
}

// air token -> per-slot-unique sentinel (count 1 => log 0 => invisible);
// else biased token (normal fp16 bit pattern).
__device__ __forceinline__ unsigned stage16(int v, int slot) {
    const bool air = (v == AIR0) | (v == AIR1) | (v == AIR2);
    return air ? (unsigned)(SENT_BASE + slot) : ((unsigned)v | 0x4000u);
}

// 128 threads, 16 patches/block (two slabs), 8 tokens/thread (8 thr/patch).
// Each patch lives entirely inside one warp's 8-lane segment, so the staging
// barrier is only __syncwarp(): warps never convoy on each other's loads.
// The single __syncthreads is pure tail (final block reduce).
__global__ __launch_bounds__(128)
void patch_entropy_fused_kernel(const int* __restrict__ s, float* __restrict__ out) {
    // patch stride 36 u32 (32 data + 4 pad = 144B): 16B-aligned, bank-spread
    __shared__ unsigned sm32[PATCHES_PER_BLOCK * 36];
    __shared__ float red_ent[4];

    const int tid = threadIdx.x;

    // ---- geometry: thread owns 8 contiguous token slots of patch pp ----
    const int pp = tid >> 3;            // 0..15
    const int r  = tid & 7;             // eighth of patch; slots 8r..8r+7
    const int d  = r >> 1;              // 0..3
    const int h0 = (r & 1) << 1;        // 0 or 2 (two h-rows)
    const int w4 = pp & 7;
    const int gslab = blockIdx.x * SLABS_PER_BLOCK + (pp >> 3);
    const int b  = gslab >> 6;
    const int pd = (gslab >> 3) & 7;
    const int ph = gslab & 7;
    const int base = b * (DD * HH * WW) + pd * (4 * HH * WW) + ph * (4 * WW)
                   + d * (HH * WW) + h0 * WW + w4 * 4;

    // ---- two LDG.128 (own 8 tokens), sentinel substitution, pack u16x2 ----
    const int4 va = *(const int4*)(s + base);
    const int4 vb = *(const int4*)(s + base + WW);
    const int slot = r << 3;
    const unsigned p0 = stage16(va.x, slot)     | (stage16(va.y, slot + 1) << 16);
    const unsigned p1 = stage16(va.z, slot + 2) | (stage16(va.w, slot + 3) << 16);
    const unsigned p2 = stage16(vb.x, slot + 4) | (stage16(vb.y, slot + 5) << 16);
    const unsigned p3 = stage16(vb.z, slot + 6) | (stage16(vb.w, slot + 7) << 16);
    *(uint4*)&sm32[pp * 36 + (r << 2)] = make_uint4(p0, p1, p2, p3);

    // probes (register-resident, no smem reload)
    const unsigned vv0 = prmt(p0, p0, 0x1010);
    const unsigned vv1 = prmt(p0, p0, 0x3232);
    const unsigned vv2 = prmt(p1, p1, 0x1010);
    const unsigned vv3 = prmt(p1, p1, 0x3232);
    const unsigned vv4 = prmt(p2, p2, 0x1010);
    const unsigned vv5 = prmt(p2, p2, 0x3232);
    const unsigned vv6 = prmt(p3, p3, 0x1010);
    const unsigned vv7 = prmt(p3, p3, 0x3232);

    // non-air among own 8 tokens (sentinel <=> staged >= SENT_BASE)
    int na = 8;
    na -= ((p0 & 0xFFFFu) >= SENT_BASE) + ((p0 >> 16) >= SENT_BASE);
    na -= ((p1 & 0xFFFFu) >= SENT_BASE) + ((p1 >> 16) >= SENT_BASE);
    na -= ((p2 & 0xFFFFu) >= SENT_BASE) + ((p2 >> 16) >= SENT_BASE);
    na -= ((p3 & 0xFFFFu) >= SENT_BASE) + ((p3 >> 16) >= SENT_BASE);

    // tot over the 8-lane patch segment (xor offsets stay in segment)
    int tot = na;
    tot += __shfl_xor_sync(0xFFFFFFFFu, tot, 1);
    tot += __shfl_xor_sync(0xFFFFFFFFu, tot, 2);
    tot += __shfl_xor_sync(0xFFFFFFFFu, tot, 4);

    // Patch data is produced and consumed entirely within this warp:
    // warp-level sync suffices — no cross-warp convoy on the slowest LDG.
    __syncwarp();

    // ---- compare core: 8x LDS.128 (pipelined) x 8 probes, f16x2 SIMD ----
    const uint4* pbase4 = (const uint4*)&sm32[pp * 36];
    unsigned acc0 = 0, acc1 = 0, acc2 = 0, acc3 = 0;
    unsigned acc4 = 0, acc5 = 0, acc6 = 0, acc7 = 0;
    uint4 u = pbase4[0];
    #pragma unroll
    for (int k = 0; k < 8; ++k) {
        const uint4 nxt = pbase4[(k + 1) & 7];   // k==7 wraps: harmless reload
        CMP8(u.x);
        CMP8(u.y);
        CMP8(u.z);
        CMP8(u.w);
        u = nxt;
    }

    // Branch-free MUFU epilogue (no LUT => no cross-warp init dependency):
    // sentinels have c==1 -> logf(1)==0 -> contribute exactly 0.
    // All-air patch: na=0, sl=0, totf=1 -> term = 0 (matches safe-divide ref).
    const float sl = __logf(h2_countf(acc0)) + __logf(h2_countf(acc1))
                   + __logf(h2_countf(acc2)) + __logf(h2_countf(acc3))
                   + __logf(h2_countf(acc4)) + __logf(h2_countf(acc5))
                   + __logf(h2_countf(acc6)) + __logf(h2_countf(acc7));
    const float totf = (float)max(tot, 1);
    const float term = __fdividef(1.0f, totf) * fmaf((float)na, __logf(totf), -sl);

    // ---- warp sum, then tail-only block reduce -> one atomic per block ----
    float x = term;
    #pragma unroll
    for (int off = 16; off > 0; off >>= 1)
        x += __shfl_xor_sync(0xFFFFFFFFu, x, off);
    const int wid = tid >> 5, lane = tid & 31;
    if (lane == 0) red_ent[wid] = x;
    __syncthreads();   // tail only — hot path already done

    if (wid == 0) {
        float y = (lane < 4) ? red_ent[lane] : 0.0f;
        y += __shfl_xor_sync(0xFFFFFFFFu, y, 2);
        y += __shfl_xor_sync(0xFFFFFFFFu, y, 1);
        if (lane == 0) {
            // Single packed atomic: sum + arrival count in one u64. Last
            // block's atomic return already holds the full sum — no fence,
            // no ticket, no re-read. Integer adds => deterministic.
            const long long sfp = (long long)((double)y * FP_SCALE);
            const unsigned long long qv =
                (unsigned long long)(sfp + (long long)BLK_BIAS) | CNT_ONE;
            const unsigned long long old = atomicAdd(&g_acc, qv);
            if ((old >> 52) == (GRID_BLOCKS - 1)) {
                const unsigned long long sum52 = (old + qv) & SUM_MASK;
                const double total =
                    ((double)(long long)(sum52 - (unsigned long long)GRID_BLOCKS * BLK_BIAS))
                    / FP_SCALE;
                out[0] = (float)(total / ((double)TOTAL_PATCHES + 1e-06));
                g_acc = 0ULL;   // self-clean for the next graph replay
            }
        }
    }
}

extern "C" void kernel_launch(void* const* d_in, const int* in_sizes, int n_in,
                              void* d_out, int out_size) {
    const int* structure = (const int*)d_in[0];
    float* out = (float*)d_out;
    patch_entropy_fused_kernel<<<GRID_BLOCKS, 128>>>(structure, out);
}